// round 6
// baseline (speedup 1.0000x reference)
#include <cuda_runtime.h>

#define BB 32
#define NN 256
#define DD 128
#define NEG_MASK (-9000000.0f)
#define LEAK 0.2f

// Scratch for masked relation scores (allowed: __device__ globals)
__device__ float g_s1[BB * NN * NN];
__device__ float g_s2[BB * NN * NN];

// ---------------------------------------------------------------------------
// f32x2 packed-math helpers
// ---------------------------------------------------------------------------
typedef unsigned long long ull;

__device__ __forceinline__ ull fma2(ull a, ull b, ull c) {
    ull d;
    asm("fma.rn.f32x2 %0, %1, %2, %3;" : "=l"(d) : "l"(a), "l"(b), "l"(c));
    return d;
}
__device__ __forceinline__ ull pack2(float lo, float hi) {
    ull d;
    asm("mov.b64 %0, {%1, %2};" : "=l"(d) : "f"(lo), "f"(hi));
    return d;
}
__device__ __forceinline__ void unpack2(ull v, float& lo, float& hi) {
    asm("mov.b64 {%0, %1}, %2;" : "=f"(lo), "=f"(hi) : "l"(v));
}

// ---------------------------------------------------------------------------
// Kernel A: masked gated relation scores (unchanged from R5-passing).
// ---------------------------------------------------------------------------
#define TI 8
#define P4 33
#define HIW_F4 (TI * 4 * (DD / 4))
#define HJ_F4 (128 * P4)
#define SMEM_BYTES ((HIW_F4 + HJ_F4) * 16)

extern __shared__ float4 sm4[];

__global__ __launch_bounds__(256, 2) void scores_kernel(
    const float* __restrict__ sem, const float* __restrict__ strv,
    const int* __restrict__ adj,
    const float* __restrict__ aw, const float* __restrict__ swt)
{
    const int b = blockIdx.y;
    const int i0 = blockIdx.x * TI;
    const int tid = threadIdx.x;

    float4* sm_hiw4 = sm4;
    float4* sm_hj4 = sm4 + HIW_F4;

    const int w8 = tid >> 5, lane = tid & 31;
    const int jgrp = w8 & 3, ibase = (w8 >> 2) * 4;
    const int jloc = jgrp * 32 + lane;

    for (int e = 0; e < 2; e++) {
        const float* h = e ? strv : sem;
        const float* wmat = e ? swt : aw;
        float* gs = e ? g_s2 : g_s1;

        __syncthreads();
        for (int idx = tid; idx < TI * 4 * DD; idx += 256) {
            int d = idx & 127;
            int r = (idx >> 7) & 3;
            int i = idx >> 9;
            ((float*)sm_hiw4)[(i * 128 + ((d >> 2) << 2) + r) * 4 + (d & 3)] =
                h[((b * NN) + i0 + i) * DD + d] * wmat[r * DD + d];
        }

        for (int c = 0; c < 2; c++) {
            __syncthreads();
            for (int idx = tid; idx < 128 * (DD / 4); idx += 256) {
                int d4 = idx & 31;
                int jl = idx >> 5;
                sm_hj4[jl * P4 + d4] =
                    ((const float4*)(h + ((b * NN) + c * 128 + jl) * DD))[d4];
            }
            __syncthreads();

            const int j = c * 128 + jloc;

            int msk[4], off[4];
#pragma unroll
            for (int ii = 0; ii < 4; ii++) {
                int a = adj[((b * NN) + i0 + ibase + ii) * NN + j];
                msk[ii] = a;
                int r = a > 0 ? a - 1 : 0;
                off[ii] = (ibase + ii) * 128 + r;
            }

            ull acc[4];
#pragma unroll
            for (int ii = 0; ii < 4; ii++) acc[ii] = 0ull;

            const ulonglong2* hiw2 = (const ulonglong2*)sm_hiw4;
            const ulonglong2* hj2 = (const ulonglong2*)sm_hj4 + jloc * P4;

#pragma unroll 8
            for (int d4 = 0; d4 < 32; d4++) {
                ulonglong2 hv = hj2[d4];
                int dbase = d4 << 2;
#pragma unroll
                for (int ii = 0; ii < 4; ii++) {
                    ulonglong2 wv = hiw2[off[ii] + dbase];
                    acc[ii] = fma2(wv.x, hv.x, acc[ii]);
                    acc[ii] = fma2(wv.y, hv.y, acc[ii]);
                }
            }

#pragma unroll
            for (int ii = 0; ii < 4; ii++) {
                float lo, hi;
                unpack2(acc[ii], lo, hi);
                float v = lo + hi;
                v = msk[ii] > 0 ? (v >= 0.f ? v : LEAK * v) : NEG_MASK;
                gs[((b * NN) + i0 + ibase + ii) * NN + j] = v;
            }
        }
    }
}

// ---------------------------------------------------------------------------
// Kernel B v2: sparse-support entmax. One thread per (row, embed).
// Candidates: Xs > max(Xs)-1 (exact: excluded terms are fp-zero for tau>=tau_lo).
// Zero shfls, zero syncs inside the 30-iter bisection.
// grid (NN/64, BB) = 128 CTAs x 128 threads.
// ---------------------------------------------------------------------------
#define CROWS 64
#define CAP 96
#define SEMP4 33
#define SEMS_BYTES (NN * SEMP4 * 16)          // 135168
#define LIST_BYTES (128 * CAP * 4)            // 49152
#define IDX_BYTES  (128 * CAP)                // 12288
#define CMB_SMEM (SEMS_BYTES + LIST_BYTES + IDX_BYTES + (128 + 128 + 128 + 64) * 4)

template <int MODE>
__device__ __forceinline__ float pfm(float t, float inv) {
    // t is already max(z, 0)
    if (MODE == 2) return t * t;     // alpha = 1.5
    if (MODE == 1) return t;         // alpha = 2.0
    return __powf(t, inv);           // generic
}

template <int MODE>
__device__ float sumP_list(const float* __restrict__ xs, int n, float tau, float inv) {
    float a0 = 0.f, a1 = 0.f, a2 = 0.f, a3 = 0.f;
    int k = 0;
    for (; k + 4 <= n; k += 4) {
        float t0 = fmaxf(xs[k]     - tau, 0.f);
        float t1 = fmaxf(xs[k + 1] - tau, 0.f);
        float t2 = fmaxf(xs[k + 2] - tau, 0.f);
        float t3 = fmaxf(xs[k + 3] - tau, 0.f);
        a0 += pfm<MODE>(t0, inv);
        a1 += pfm<MODE>(t1, inv);
        a2 += pfm<MODE>(t2, inv);
        a3 += pfm<MODE>(t3, inv);
    }
    for (; k < n; k++) a0 += pfm<MODE>(fmaxf(xs[k] - tau, 0.f), inv);
    return (a0 + a1) + (a2 + a3);
}

template <int MODE>
__device__ float sumP_raw(const float4* __restrict__ g4, float am1, float tau, float inv) {
    float a0 = 0.f, a1 = 0.f, a2 = 0.f, a3 = 0.f;
    for (int k = 0; k < NN / 4; k++) {
        float4 v = g4[k];
        a0 += pfm<MODE>(fmaxf(__fmul_rn(v.x, am1) - tau, 0.f), inv);
        a1 += pfm<MODE>(fmaxf(__fmul_rn(v.y, am1) - tau, 0.f), inv);
        a2 += pfm<MODE>(fmaxf(__fmul_rn(v.z, am1) - tau, 0.f), inv);
        a3 += pfm<MODE>(fmaxf(__fmul_rn(v.w, am1) - tau, 0.f), inv);
    }
    return (a0 + a1) + (a2 + a3);
}

template <int MODE>
__device__ void entmax_thread(const float* __restrict__ gsrow, float am1, float inv,
                              float* __restrict__ myXs, unsigned char* __restrict__ myIdx,
                              float& tauOut, float& Sout, int& cntOut)
{
    const float4* g4 = (const float4*)gsrow;

    // Pass 1: row max (monotone mul => max(X)*am1 == max(X*am1) exactly)
    float mx = -3.4e38f;
    for (int k = 0; k < NN / 4; k++) {
        float4 v = g4[k];
        mx = fmaxf(mx, fmaxf(fmaxf(v.x, v.y), fmaxf(v.z, v.w)));
    }
    float mxS = __fmul_rn(mx, am1);
    float thr = mxS - 1.f;     // tau_lo

    // Pass 2: compact candidates Xs > tau_lo (others are exact zeros forever)
    int cnt = 0;
    for (int k = 0; k < NN / 4; k++) {
        float4 v = g4[k];
        float x0 = __fmul_rn(v.x, am1);
        float x1 = __fmul_rn(v.y, am1);
        float x2 = __fmul_rn(v.z, am1);
        float x3 = __fmul_rn(v.w, am1);
        if (x0 > thr) { if (cnt < CAP) { myXs[cnt] = x0; myIdx[cnt] = (unsigned char)(4 * k);     } cnt++; }
        if (x1 > thr) { if (cnt < CAP) { myXs[cnt] = x1; myIdx[cnt] = (unsigned char)(4 * k + 1); } cnt++; }
        if (x2 > thr) { if (cnt < CAP) { myXs[cnt] = x2; myIdx[cnt] = (unsigned char)(4 * k + 2); } cnt++; }
        if (x3 > thr) { if (cnt < CAP) { myXs[cnt] = x3; myIdx[cnt] = (unsigned char)(4 * k + 3); } cnt++; }
    }
    bool ovf = cnt > CAP;

    float tau = thr;
    float dm = 1.f - exp2f(-8.f * am1);   // tau_hi - tau_lo
    float flo = (ovf ? sumP_raw<MODE>(g4, am1, tau, inv)
                     : sumP_list<MODE>(myXs, cnt, tau, inv)) - 1.f;

#pragma unroll 1
    for (int it = 0; it < 30; it++) {
        dm *= 0.5f;
        float tm = tau + dm;
        float f = (ovf ? sumP_raw<MODE>(g4, am1, tm, inv)
                       : sumP_list<MODE>(myXs, cnt, tm, inv)) - 1.f;
        if (f * flo >= 0.f) tau = tm;
    }

    Sout = ovf ? sumP_raw<MODE>(g4, am1, tau, inv)
               : sumP_list<MODE>(myXs, cnt, tau, inv);
    tauOut = tau;
    cntOut = ovf ? -1 : cnt;
}

template <int M1, int M2>
__device__ void wf_phase(int tid, int b, int i0,
                         float am1_1, float am1_2, float inv1, float inv2,
                         float* __restrict__ myXs, unsigned char* __restrict__ myIdx,
                         const float* __restrict__ tauA, const float* __restrict__ SA,
                         const int* __restrict__ cntA, float* __restrict__ scaleA)
{
    float tau1 = tauA[tid], S1 = SA[tid];
    int c1 = cntA[tid];
    float tau2 = tauA[64 + tid], S2 = SA[64 + tid];
    const float* gs2row = g_s2 + ((b * NN) + i0 + tid) * NN;
    float* g1row = g_s1 + ((b * NN) + i0 + tid) * NN;
    float S3 = 0.f;

    if (c1 >= 0) {
        for (int k = 0; k < c1; k++) {
            float p1 = pfm<M1>(fmaxf(myXs[k] - tau1, 0.f), inv1);
            int j = myIdx[k];
            float p2 = pfm<M2>(fmaxf(__fmul_rn(gs2row[j], am1_2) - tau2, 0.f), inv2);
            float wf = p1 * p2;
            S3 += wf;
            myXs[k] = wf;   // overwrite Xs slot with wf for GEMV
        }
    } else {
        // overflow fallback: materialize full wf row into g_s1 (raw no longer needed)
        for (int j = 0; j < NN; j++) {
            float p1 = pfm<M1>(fmaxf(__fmul_rn(g1row[j], am1_1) - tau1, 0.f), inv1);
            float p2 = pfm<M2>(fmaxf(__fmul_rn(gs2row[j], am1_2) - tau2, 0.f), inv2);
            float wf = p1 * p2;
            S3 += wf;
            g1row[j] = wf;
        }
    }
    // weight = p1p2/(S1S2) / (S3/(S1S2) + 1e-7) = p1p2 / (S3 + 1e-7*S1*S2)
    scaleA[tid] = 1.f / (S3 + 1e-7f * S1 * S2);
}

extern __shared__ unsigned char smemB[];

__global__ __launch_bounds__(128, 1) void combine2_kernel(
    const float* __restrict__ sem,
    const float* __restrict__ alpha1p, const float* __restrict__ alpha2p,
    float* __restrict__ out)
{
    float4* semS = (float4*)smemB;
    float* listXs = (float*)(smemB + SEMS_BYTES);
    unsigned char* listIdx = smemB + SEMS_BYTES + LIST_BYTES;
    float* tauA = (float*)(smemB + SEMS_BYTES + LIST_BYTES + IDX_BYTES);
    float* SA = tauA + 128;
    int* cntA = (int*)(SA + 128);
    float* scaleA = (float*)(cntA + 128);

    const int b = blockIdx.y, i0 = blockIdx.x * CROWS;
    const int tid = threadIdx.x;
    const int e = tid >> 6, rowLocal = tid & 63;

    // Stage sem[b] (used by GEMV only, after the sync)
    const float4* semG = (const float4*)(sem + b * NN * DD);
    for (int t = tid; t < NN * 32; t += 128) {
        int j = t >> 5, d4 = t & 31;
        semS[j * SEMP4 + d4] = semG[j * 32 + d4];
    }

    float a1 = alpha1p[0], a2 = alpha2p[0];
    float am1_1 = a1 - 1.f, am1_2 = a2 - 1.f;
    float inv1 = 1.f / am1_1, inv2 = 1.f / am1_2;
    int m1 = (fabsf(a1 - 1.5f) < 1e-4f) ? 2 : ((fabsf(a1 - 2.f) < 1e-4f) ? 1 : 0);
    int m2 = (fabsf(a2 - 1.5f) < 1e-4f) ? 2 : ((fabsf(a2 - 2.f) < 1e-4f) ? 1 : 0);

    float am1 = e ? am1_2 : am1_1;
    float inv = e ? inv2 : inv1;
    int mode = e ? m2 : m1;

    const float* gsrow = (e ? g_s2 : g_s1) + ((b * NN) + i0 + rowLocal) * NN;
    float* myXs = listXs + tid * CAP;
    unsigned char* myIdx = listIdx + tid * CAP;

    float tau, S;
    int cnt;
    if (mode == 2)      entmax_thread<2>(gsrow, am1, inv, myXs, myIdx, tau, S, cnt);
    else if (mode == 1) entmax_thread<1>(gsrow, am1, inv, myXs, myIdx, tau, S, cnt);
    else                entmax_thread<0>(gsrow, am1, inv, myXs, myIdx, tau, S, cnt);
    tauA[tid] = tau;
    SA[tid] = S;
    cntA[tid] = cnt;
    __syncthreads();

    // wf phase: sem-side threads only
    if (tid < 64) {
        if (m1 == 2 && m2 == 1)
            wf_phase<2, 1>(tid, b, i0, am1_1, am1_2, inv1, inv2, myXs, myIdx, tauA, SA, cntA, scaleA);
        else if (m1 == 1 && m2 == 2)
            wf_phase<1, 2>(tid, b, i0, am1_1, am1_2, inv1, inv2, myXs, myIdx, tauA, SA, cntA, scaleA);
        else if (m1 == 2 && m2 == 2)
            wf_phase<2, 2>(tid, b, i0, am1_1, am1_2, inv1, inv2, myXs, myIdx, tauA, SA, cntA, scaleA);
        else if (m1 == 1 && m2 == 1)
            wf_phase<1, 1>(tid, b, i0, am1_1, am1_2, inv1, inv2, myXs, myIdx, tauA, SA, cntA, scaleA);
        else
            wf_phase<0, 0>(tid, b, i0, am1_1, am1_2, inv1, inv2, myXs, myIdx, tauA, SA, cntA, scaleA);
    }
    __syncthreads();

    // Sparse GEMV: warp per row, lane = d4 (conflict-free consecutive LDS.128)
    const int w = tid >> 5, lane = tid & 31;
    const ulonglong2* semS2 = (const ulonglong2*)semS;
    for (int rr = w; rr < CROWS; rr += 4) {
        int c1 = cntA[rr];
        bool ovf = c1 < 0;
        int n = ovf ? NN : c1;
        const float* wfl = listXs + rr * CAP;
        const unsigned char* jl = listIdx + rr * CAP;
        const float* g1row = g_s1 + ((b * NN) + i0 + rr) * NN;
        ull accA = 0ull, accB = 0ull;
#pragma unroll 1
        for (int k = 0; k < n; k++) {
            int j;
            float wf;
            if (ovf) { j = k; wf = g1row[k]; }
            else     { j = jl[k]; wf = wfl[k]; }
            ulonglong2 vv = semS2[j * SEMP4 + lane];
            ull wv = pack2(wf, wf);
            accA = fma2(wv, vv.x, accA);
            accB = fma2(wv, vv.y, accB);
        }
        float sc = scaleA[rr];
        float4 o;
        unpack2(accA, o.x, o.y);
        unpack2(accB, o.z, o.w);
        o.x *= sc; o.y *= sc; o.z *= sc; o.w *= sc;
        ((float4*)out)[((b * NN) + i0 + rr) * 32 + lane] = o;
    }
}

// ---------------------------------------------------------------------------
extern "C" void kernel_launch(void* const* d_in, const int* in_sizes, int n_in,
                              void* d_out, int out_size)
{
    const float* sem  = (const float*)d_in[0];
    const float* strv = (const float*)d_in[1];
    const int*   adj  = (const int*)d_in[2];
    const float* aw   = (const float*)d_in[3];
    const float* swt  = (const float*)d_in[4];
    const float* a1   = (const float*)d_in[5];
    const float* a2   = (const float*)d_in[6];
    float* out = (float*)d_out;

    cudaFuncSetAttribute(scores_kernel,
                         cudaFuncAttributeMaxDynamicSharedMemorySize, SMEM_BYTES);
    cudaFuncSetAttribute(combine2_kernel,
                         cudaFuncAttributeMaxDynamicSharedMemorySize, CMB_SMEM);

    scores_kernel<<<dim3(NN / TI, BB), 256, SMEM_BYTES>>>(
        sem, strv, adj, aw, swt);
    combine2_kernel<<<dim3(NN / CROWS, BB), 128, CMB_SMEM>>>(sem, a1, a2, out);
}

// round 7
// speedup vs baseline: 1.5881x; 1.5881x over previous
#include <cuda_runtime.h>

#define BB 32
#define NN 256
#define DD 128
#define NEG_MASK (-9000000.0f)
#define LEAK 0.2f

// Scratch for masked relation scores (allowed: __device__ globals)
__device__ float g_s1[BB * NN * NN];
__device__ float g_s2[BB * NN * NN];

// ---------------------------------------------------------------------------
// f32x2 packed-math helpers
// ---------------------------------------------------------------------------
typedef unsigned long long ull;

__device__ __forceinline__ ull fma2(ull a, ull b, ull c) {
    ull d;
    asm("fma.rn.f32x2 %0, %1, %2, %3;" : "=l"(d) : "l"(a), "l"(b), "l"(c));
    return d;
}
__device__ __forceinline__ ull pack2(float lo, float hi) {
    ull d;
    asm("mov.b64 %0, {%1, %2};" : "=l"(d) : "f"(lo), "f"(hi));
    return d;
}
__device__ __forceinline__ void unpack2(ull v, float& lo, float& hi) {
    asm("mov.b64 {%0, %1}, %2;" : "=f"(lo), "=f"(hi) : "l"(v));
}

// ---------------------------------------------------------------------------
// Kernel A: masked gated relation scores (unchanged — verified R5/R6).
// ---------------------------------------------------------------------------
#define TI 8
#define P4 33
#define HIW_F4 (TI * 4 * (DD / 4))
#define HJ_F4 (128 * P4)
#define SMEM_BYTES ((HIW_F4 + HJ_F4) * 16)

extern __shared__ float4 sm4[];

__global__ __launch_bounds__(256, 2) void scores_kernel(
    const float* __restrict__ sem, const float* __restrict__ strv,
    const int* __restrict__ adj,
    const float* __restrict__ aw, const float* __restrict__ swt)
{
    const int b = blockIdx.y;
    const int i0 = blockIdx.x * TI;
    const int tid = threadIdx.x;

    float4* sm_hiw4 = sm4;
    float4* sm_hj4 = sm4 + HIW_F4;

    const int w8 = tid >> 5, lane = tid & 31;
    const int jgrp = w8 & 3, ibase = (w8 >> 2) * 4;
    const int jloc = jgrp * 32 + lane;

    for (int e = 0; e < 2; e++) {
        const float* h = e ? strv : sem;
        const float* wmat = e ? swt : aw;
        float* gs = e ? g_s2 : g_s1;

        __syncthreads();
        for (int idx = tid; idx < TI * 4 * DD; idx += 256) {
            int d = idx & 127;
            int r = (idx >> 7) & 3;
            int i = idx >> 9;
            ((float*)sm_hiw4)[(i * 128 + ((d >> 2) << 2) + r) * 4 + (d & 3)] =
                h[((b * NN) + i0 + i) * DD + d] * wmat[r * DD + d];
        }

        for (int c = 0; c < 2; c++) {
            __syncthreads();
            for (int idx = tid; idx < 128 * (DD / 4); idx += 256) {
                int d4 = idx & 31;
                int jl = idx >> 5;
                sm_hj4[jl * P4 + d4] =
                    ((const float4*)(h + ((b * NN) + c * 128 + jl) * DD))[d4];
            }
            __syncthreads();

            const int j = c * 128 + jloc;

            int msk[4], off[4];
#pragma unroll
            for (int ii = 0; ii < 4; ii++) {
                int a = adj[((b * NN) + i0 + ibase + ii) * NN + j];
                msk[ii] = a;
                int r = a > 0 ? a - 1 : 0;
                off[ii] = (ibase + ii) * 128 + r;
            }

            ull acc[4];
#pragma unroll
            for (int ii = 0; ii < 4; ii++) acc[ii] = 0ull;

            const ulonglong2* hiw2 = (const ulonglong2*)sm_hiw4;
            const ulonglong2* hj2 = (const ulonglong2*)sm_hj4 + jloc * P4;

#pragma unroll 8
            for (int d4 = 0; d4 < 32; d4++) {
                ulonglong2 hv = hj2[d4];
                int dbase = d4 << 2;
#pragma unroll
                for (int ii = 0; ii < 4; ii++) {
                    ulonglong2 wv = hiw2[off[ii] + dbase];
                    acc[ii] = fma2(wv.x, hv.x, acc[ii]);
                    acc[ii] = fma2(wv.y, hv.y, acc[ii]);
                }
            }

#pragma unroll
            for (int ii = 0; ii < 4; ii++) {
                float lo, hi;
                unpack2(acc[ii], lo, hi);
                float v = lo + hi;
                v = msk[ii] > 0 ? (v >= 0.f ? v : LEAK * v) : NEG_MASK;
                gs[((b * NN) + i0 + ibase + ii) * NN + j] = v;
            }
        }
    }
}

// ---------------------------------------------------------------------------
// Kernel B v3: sparse-support entmax with warp-parallel groups.
// 16 rows/CTA, 2 rows/warp, 16-lane group per row. grid (16, 32) = 512 CTAs.
// ---------------------------------------------------------------------------
#define CROWS2 16
#define LCAP 144
#define LSTRIDE 164     // row stride (floats) -> conflict-free across groups

__device__ __forceinline__ float gsum16(float v) {
#pragma unroll
    for (int o = 1; o < 16; o <<= 1) v += __shfl_xor_sync(0xffffffffu, v, o);
    return v;
}
__device__ __forceinline__ float gmax16(float v) {
#pragma unroll
    for (int o = 1; o < 16; o <<= 1) v = fmaxf(v, __shfl_xor_sync(0xffffffffu, v, o));
    return v;
}

template <int MODE>
__device__ __forceinline__ float pfm(float t, float inv) {
    // t is already max(z, 0)
    if (MODE == 2) return t * t;     // alpha = 1.5
    if (MODE == 1) return t;         // alpha = 2.0
    return __powf(t, inv);           // generic
}

template <int MODE>
__device__ __forceinline__ float evalList(const float* __restrict__ vrow,
                                          int n16, int s, float tau, float inv) {
    float a = 0.f;
    for (int k = s; k < n16; k += 16)
        a += pfm<MODE>(fmaxf(vrow[k] - tau, 0.f), inv);
    return a;
}

template <int MODE>
__device__ __forceinline__ float evalDense(const float4* __restrict__ X,
                                           float tau, float inv) {
    float a0 = 0.f, a1 = 0.f, a2 = 0.f, a3 = 0.f;
#pragma unroll
    for (int t = 0; t < 4; t++) {
        a0 += pfm<MODE>(fmaxf(X[t].x - tau, 0.f), inv);
        a1 += pfm<MODE>(fmaxf(X[t].y - tau, 0.f), inv);
        a2 += pfm<MODE>(fmaxf(X[t].z - tau, 0.f), inv);
        a3 += pfm<MODE>(fmaxf(X[t].w - tau, 0.f), inv);
    }
    return (a0 + a1) + (a2 + a3);
}

template <int M1, int M2>
__device__ void cwork(const float* __restrict__ sem, float* __restrict__ out,
                      int b, int i0, int tid,
                      float am1_1, float am1_2, float inv1, float inv2,
                      float (*sVal1)[LSTRIDE], float (*sVal2)[LSTRIDE],
                      unsigned char (*sIdx1)[LSTRIDE],
                      float (*sDWF)[NN], int* sN1, float* sScale)
{
    const int w = tid >> 5, lane = tid & 31;
    const int g = lane >> 4, s = lane & 15;
    const int r = 2 * w + g;
    const int row = i0 + r;

    const float4* x1g = (const float4*)(g_s1 + ((b * NN) + row) * NN);
    const float4* x2g = (const float4*)(g_s2 + ((b * NN) + row) * NN);

    // Load + scale (FMUL.RN, same as reference Xs = X*(alpha-1))
    float4 X1[4], X2[4];
    float mx1 = -3.4e38f, mx2 = -3.4e38f;
#pragma unroll
    for (int t = 0; t < 4; t++) {
        float4 v = x1g[s + 16 * t];
        v.x *= am1_1; v.y *= am1_1; v.z *= am1_1; v.w *= am1_1;
        X1[t] = v;
        mx1 = fmaxf(mx1, fmaxf(fmaxf(v.x, v.y), fmaxf(v.z, v.w)));
        float4 u = x2g[s + 16 * t];
        u.x *= am1_2; u.y *= am1_2; u.z *= am1_2; u.w *= am1_2;
        X2[t] = u;
        mx2 = fmaxf(mx2, fmaxf(fmaxf(u.x, u.y), fmaxf(u.z, u.w)));
    }
    mx1 = gmax16(mx1);
    mx2 = gmax16(mx2);
    const float thr1 = mx1 - 1.f, thr2 = mx2 - 1.f;   // tau_lo

    // Count candidates (Xs > tau_lo; excluded terms are exact zeros forever)
    int c1 = 0, c2 = 0;
#pragma unroll
    for (int t = 0; t < 4; t++) {
        c1 += (X1[t].x > thr1) + (X1[t].y > thr1) + (X1[t].z > thr1) + (X1[t].w > thr1);
        c2 += (X2[t].x > thr2) + (X2[t].y > thr2) + (X2[t].z > thr2) + (X2[t].w > thr2);
    }
    // One packed inclusive scan for both embeds across the 16-lane group
    int incl = c1 | (c2 << 16);
#pragma unroll
    for (int o = 1; o < 16; o <<= 1) {
        int u = __shfl_up_sync(0xffffffffu, incl, o);
        if (s >= o) incl += u;
    }
    int tot = __shfl_sync(0xffffffffu, incl, (lane & 16) | 15);
    const int ntot1 = tot & 0xffff, ntot2 = tot >> 16;
    const int pfx1 = (incl & 0xffff) - c1, pfx2 = (incl >> 16) - c2;

    const bool ok1 = ntot1 <= LCAP, ok2 = ntot2 <= LCAP;
    const int n16_1 = (ntot1 + 15) & ~15, n16_2 = (ntot2 + 15) & ~15;

    if (ok1) {
        int pos = pfx1;
#pragma unroll
        for (int t = 0; t < 4; t++) {
            int jb = 4 * (s + 16 * t);
            if (X1[t].x > thr1) { sVal1[r][pos] = X1[t].x; sIdx1[r][pos] = (unsigned char)jb;       pos++; }
            if (X1[t].y > thr1) { sVal1[r][pos] = X1[t].y; sIdx1[r][pos] = (unsigned char)(jb + 1); pos++; }
            if (X1[t].z > thr1) { sVal1[r][pos] = X1[t].z; sIdx1[r][pos] = (unsigned char)(jb + 2); pos++; }
            if (X1[t].w > thr1) { sVal1[r][pos] = X1[t].w; sIdx1[r][pos] = (unsigned char)(jb + 3); pos++; }
        }
        for (int p = ntot1 + s; p < n16_1; p += 16) { sVal1[r][p] = thr1; sIdx1[r][p] = 0; }
    }
    if (ok2) {
        int pos = pfx2;
#pragma unroll
        for (int t = 0; t < 4; t++) {
            if (X2[t].x > thr2) sVal2[r][pos++] = X2[t].x;
            if (X2[t].y > thr2) sVal2[r][pos++] = X2[t].y;
            if (X2[t].z > thr2) sVal2[r][pos++] = X2[t].z;
            if (X2[t].w > thr2) sVal2[r][pos++] = X2[t].w;
        }
        for (int p = ntot2 + s; p < n16_2; p += 16) sVal2[r][p] = thr2;
    }
    __syncwarp();

    // 30-iteration bisection (reference-faithful; pads contribute exact 0)
    float tau1 = thr1, tau2 = thr2;
    float dm1 = 1.f - exp2f(-8.f * am1_1);
    float dm2 = 1.f - exp2f(-8.f * am1_2);

    float f1 = ok1 ? evalList<M1>(sVal1[r], n16_1, s, tau1, inv1)
                   : evalDense<M1>(X1, tau1, inv1);
    float f2 = ok2 ? evalList<M2>(sVal2[r], n16_2, s, tau2, inv2)
                   : evalDense<M2>(X2, tau2, inv2);
    const float flo1 = gsum16(f1) - 1.f;
    const float flo2 = gsum16(f2) - 1.f;

#pragma unroll 1
    for (int it = 0; it < 30; it++) {
        dm1 *= 0.5f;
        dm2 *= 0.5f;
        float tm1 = tau1 + dm1, tm2 = tau2 + dm2;
        float a = ok1 ? evalList<M1>(sVal1[r], n16_1, s, tm1, inv1)
                      : evalDense<M1>(X1, tm1, inv1);
        float bsum = ok2 ? evalList<M2>(sVal2[r], n16_2, s, tm2, inv2)
                         : evalDense<M2>(X2, tm2, inv2);
        a = gsum16(a);
        bsum = gsum16(bsum);
        if ((a - 1.f) * flo1 >= 0.f) tau1 = tm1;
        if ((bsum - 1.f) * flo2 >= 0.f) tau2 = tm2;
    }

    const float S1 = gsum16(ok1 ? evalList<M1>(sVal1[r], n16_1, s, tau1, inv1)
                                : evalDense<M1>(X1, tau1, inv1));
    const float S2 = gsum16(ok2 ? evalList<M2>(sVal2[r], n16_2, s, tau2, inv2)
                                : evalDense<M2>(X2, tau2, inv2));

    // wf = p1*p2 phase (supp(wf) within list1)
    float s3p = 0.f;
    if (ok1) {
        const float* g2row = g_s2 + ((b * NN) + row) * NN;
        for (int k = s; k < n16_1; k += 16) {
            float p1 = pfm<M1>(fmaxf(sVal1[r][k] - tau1, 0.f), inv1);
            int j = sIdx1[r][k];
            float x2 = __fmul_rn(g2row[j], am1_2);
            float p2 = pfm<M2>(fmaxf(x2 - tau2, 0.f), inv2);
            float wf = p1 * p2;
            s3p += wf;
            sVal1[r][k] = wf;
        }
    } else {
#pragma unroll
        for (int t = 0; t < 4; t++) {
            int jb = 4 * (s + 16 * t);
            float w0 = pfm<M1>(fmaxf(X1[t].x - tau1, 0.f), inv1) * pfm<M2>(fmaxf(X2[t].x - tau2, 0.f), inv2);
            float w1 = pfm<M1>(fmaxf(X1[t].y - tau1, 0.f), inv1) * pfm<M2>(fmaxf(X2[t].y - tau2, 0.f), inv2);
            float w2 = pfm<M1>(fmaxf(X1[t].z - tau1, 0.f), inv1) * pfm<M2>(fmaxf(X2[t].z - tau2, 0.f), inv2);
            float w3 = pfm<M1>(fmaxf(X1[t].w - tau1, 0.f), inv1) * pfm<M2>(fmaxf(X2[t].w - tau2, 0.f), inv2);
            *(float4*)&sDWF[r][jb] = make_float4(w0, w1, w2, w3);
            s3p += (w0 + w1) + (w2 + w3);
        }
    }
    float s3 = gsum16(s3p);
    if (s == 0) {
        sN1[r] = ok1 ? ntot1 : -1;
        // weight = p1p2/(S1S2) / (S3/(S1S2)+1e-7) = p1p2 / (S3 + 1e-7 S1 S2)
        sScale[r] = 1.f / (s3 + 1e-7f * S1 * S2);
    }
    __syncwarp();

    // Output GEMV: warp-wide per row, lane = d4 (sem[b] is L1-resident)
    const ulonglong2* semb2 = (const ulonglong2*)(sem + b * NN * DD);
#pragma unroll
    for (int q = 0; q < 2; q++) {
        int rr = 2 * w + q;
        int n1 = sN1[rr];
        float sc = sScale[rr];
        ull accA = 0ull, accB = 0ull;
        if (n1 >= 0) {
#pragma unroll 1
            for (int k = 0; k < n1; k++) {
                float wf = sVal1[rr][k];
                int j = sIdx1[rr][k];
                ulonglong2 vv = semb2[j * 32 + lane];
                ull wv = pack2(wf, wf);
                accA = fma2(wv, vv.x, accA);
                accB = fma2(wv, vv.y, accB);
            }
        } else {
#pragma unroll 1
            for (int j = 0; j < NN; j++) {
                float wf = sDWF[rr][j];
                ulonglong2 vv = semb2[j * 32 + lane];
                ull wv = pack2(wf, wf);
                accA = fma2(wv, vv.x, accA);
                accB = fma2(wv, vv.y, accB);
            }
        }
        float4 o;
        unpack2(accA, o.x, o.y);
        unpack2(accB, o.z, o.w);
        o.x *= sc; o.y *= sc; o.z *= sc; o.w *= sc;
        ((float4*)out)[((b * NN) + i0 + rr) * 32 + lane] = o;
    }
}

__global__ __launch_bounds__(256, 2) void combine3_kernel(
    const float* __restrict__ sem,
    const float* __restrict__ alpha1p, const float* __restrict__ alpha2p,
    float* __restrict__ out)
{
    __shared__ float sVal1[CROWS2][LSTRIDE];
    __shared__ float sVal2[CROWS2][LSTRIDE];
    __shared__ unsigned char sIdx1[CROWS2][LSTRIDE];
    __shared__ float sDWF[CROWS2][NN];
    __shared__ int sN1[CROWS2];
    __shared__ float sScale[CROWS2];

    const int b = blockIdx.y, i0 = blockIdx.x * CROWS2;
    const int tid = threadIdx.x;

    float a1 = alpha1p[0], a2 = alpha2p[0];
    float am1_1 = a1 - 1.f, am1_2 = a2 - 1.f;
    float inv1 = 1.f / am1_1, inv2 = 1.f / am1_2;
    int m1 = (fabsf(a1 - 1.5f) < 1e-4f) ? 2 : ((fabsf(a1 - 2.f) < 1e-4f) ? 1 : 0);
    int m2 = (fabsf(a2 - 1.5f) < 1e-4f) ? 2 : ((fabsf(a2 - 2.f) < 1e-4f) ? 1 : 0);

    if (m1 == 2 && m2 == 1)
        cwork<2, 1>(sem, out, b, i0, tid, am1_1, am1_2, inv1, inv2,
                    sVal1, sVal2, sIdx1, sDWF, sN1, sScale);
    else if (m1 == 1 && m2 == 2)
        cwork<1, 2>(sem, out, b, i0, tid, am1_1, am1_2, inv1, inv2,
                    sVal1, sVal2, sIdx1, sDWF, sN1, sScale);
    else if (m1 == 2 && m2 == 2)
        cwork<2, 2>(sem, out, b, i0, tid, am1_1, am1_2, inv1, inv2,
                    sVal1, sVal2, sIdx1, sDWF, sN1, sScale);
    else if (m1 == 1 && m2 == 1)
        cwork<1, 1>(sem, out, b, i0, tid, am1_1, am1_2, inv1, inv2,
                    sVal1, sVal2, sIdx1, sDWF, sN1, sScale);
    else
        cwork<0, 0>(sem, out, b, i0, tid, am1_1, am1_2, inv1, inv2,
                    sVal1, sVal2, sIdx1, sDWF, sN1, sScale);
}

// ---------------------------------------------------------------------------
extern "C" void kernel_launch(void* const* d_in, const int* in_sizes, int n_in,
                              void* d_out, int out_size)
{
    const float* sem  = (const float*)d_in[0];
    const float* strv = (const float*)d_in[1];
    const int*   adj  = (const int*)d_in[2];
    const float* aw   = (const float*)d_in[3];
    const float* swt  = (const float*)d_in[4];
    const float* a1   = (const float*)d_in[5];
    const float* a2   = (const float*)d_in[6];
    float* out = (float*)d_out;

    cudaFuncSetAttribute(scores_kernel,
                         cudaFuncAttributeMaxDynamicSharedMemorySize, SMEM_BYTES);

    scores_kernel<<<dim3(NN / TI, BB), 256, SMEM_BYTES>>>(
        sem, strv, adj, aw, swt);
    combine3_kernel<<<dim3(NN / CROWS2, BB), 256>>>(sem, a1, a2, out);
}